// round 5
// baseline (speedup 1.0000x reference)
#include <cuda_runtime.h>
#include <cstdint>

#define S_LEN 4096
#define EMB   1024
#define HALF  512
#define NHEAD 16
#define DH    32

// Scratch buffers (tf32 bit patterns stored as uint32)
__device__ uint32_t g_xt[S_LEN * HALF];          // x left half, GEMM-A perm
__device__ uint32_t g_wt[(3 * HALF + EMB) * HALF]; // Wq|Wk|Wv|Wo, GEMM-B perm
__device__ float    g_q [S_LEN * HALF];          // plain float
__device__ uint32_t g_k [S_LEN * HALF];          // K-perm tf32 (GEMM-A/B perm per head chunk)
__device__ uint32_t g_v [S_LEN * HALF];          // V-perm tf32
__device__ uint32_t g_at[S_LEN * HALF];          // attention out, GEMM-A perm tf32

__device__ __forceinline__ uint32_t f2tf32(float x) {
    uint32_t y;
    asm("cvt.rna.tf32.f32 %0, %1;" : "=r"(y) : "f"(x));
    return y;
}
__device__ __forceinline__ float ex2(float x) {
    float y;
    asm("ex2.approx.f32 %0, %1;" : "=f"(y) : "f"(x));
    return y;
}

// m16n8k8 tf32 mma. A: a0=(g,c) a1=(g+8,c) a2=(g,c+4) a3=(g+8,c+4)
// B: b0=(k=c,n=g) b1=(k=c+4,n=g); C: c0=(g,2c) c1=(g,2c+1) c2=(g+8,2c) c3=(g+8,2c+1)
__device__ __forceinline__ void mma_tf32(float* d, const uint32_t* a, const uint32_t* b) {
    asm volatile(
        "mma.sync.aligned.m16n8k8.row.col.f32.tf32.tf32.f32 "
        "{%0,%1,%2,%3}, {%4,%5,%6,%7}, {%8,%9}, {%0,%1,%2,%3};"
        : "+f"(d[0]), "+f"(d[1]), "+f"(d[2]), "+f"(d[3])
        : "r"(a[0]), "r"(a[1]), "r"(a[2]), "r"(a[3]), "r"(b[0]), "r"(b[1]));
}

// =====================   conversion prologues   ============================
// Perm within each 32-col chunk: word p holds k(p) = (p>>3) + (p&7)*4
__global__ void __launch_bounds__(256) conv_x_kernel(const float* __restrict__ x)
{
    int idx = blockIdx.x * 256 + threadIdx.x;        // 0..524287
    int p4 = idx * 4;
    int r = p4 >> 9;
    int col = p4 & 511;
    int base = col & ~31;
    int pp = col & 31;
    const float* src = x + (size_t)r * EMB + base;   // left half only
    uint32_t w[4];
#pragma unroll
    for (int j = 0; j < 4; j++) {
        int p = pp + j;
        int k = (p >> 3) + (p & 7) * 4;
        w[j] = f2tf32(src[k]);
    }
    *(uint4*)&g_xt[(size_t)r * HALF + col] = make_uint4(w[0], w[1], w[2], w[3]);
}

__global__ void __launch_bounds__(256) conv_w_kernel(
    const float* __restrict__ Wq, const float* __restrict__ Wk,
    const float* __restrict__ Wv, const float* __restrict__ Wo)
{
    int idx = blockIdx.x * 256 + threadIdx.x;        // 0..327679
    int p4 = idx * 4;
    int r = p4 >> 9;
    int col = p4 & 511;
    const float* src;
    if (r < 512)       src = Wq + (size_t)r * HALF;
    else if (r < 1024) src = Wk + (size_t)(r - 512) * HALF;
    else if (r < 1536) src = Wv + (size_t)(r - 1024) * HALF;
    else               src = Wo + (size_t)(r - 1536) * HALF;
    int base = col & ~31;
    int pp = col & 31;
    uint32_t w[4];
#pragma unroll
    for (int j = 0; j < 4; j++) {
        int p = pp + j;
        int k = (p >> 3) + (p & 7) * 4;
        w[j] = f2tf32(src[base + k]);
    }
    *(uint4*)&g_wt[(size_t)r * HALF + col] = make_uint4(w[0], w[1], w[2], w[3]);
}

// =====================   TF32 GEMM (pre-converted inputs)   ================
// CTA 128x64, BK=32, 256 thr, warp tile 32x32. Double-buffered smem.
// MODE 0: plain float (g_q). 1: K-perm tf32. 2: V-perm tf32. 3: float+bias.
#define GPAD 36

template <int MODE>
__device__ __forceinline__ void gemm_body(
    const uint32_t* __restrict__ A, int lda,
    const uint32_t* __restrict__ B, int ldb,
    void* __restrict__ Cout, int ldc,
    const float* __restrict__ bias, int K)
{
    extern __shared__ uint32_t gsm[];   // [As0 4608][Bs0 2304][As1][Bs1]

    const int t = threadIdx.x;
    const int lane = t & 31;
    const int w = t >> 5;
    const int wm = (w & 3) * 32;
    const int wn = (w >> 2) * 32;
    const int g = lane >> 2;
    const int c = lane & 3;
    const int m0 = blockIdx.x * 128;
    const int n0 = blockIdx.y * 64;

    const int lr = t >> 3;        // 0..31
    const int q  = t & 7;
    const int lc = q * 4;

    uint4 pa[4], pb[2];
#pragma unroll
    for (int i = 0; i < 4; i++)
        pa[i] = *(const uint4*)&A[(size_t)(m0 + lr + i * 32) * lda + lc];
#pragma unroll
    for (int i = 0; i < 2; i++)
        pb[i] = *(const uint4*)&B[(size_t)(n0 + lr + i * 32) * ldb + lc];

    {
        uint32_t* As = gsm;
        uint32_t* Bs = gsm + 4608;
#pragma unroll
        for (int i = 0; i < 4; i++)
            *(uint4*)&As[(lr + i * 32) * GPAD + lc] = pa[i];
#pragma unroll
        for (int i = 0; i < 2; i++)
            *(uint4*)&Bs[(lr + i * 32) * GPAD + lc] = pb[i];
    }

    float acc[2][4][4] = {};
    const int NT = K / 32;

    for (int i = 0; i < NT; i++) {
        __syncthreads();
        uint32_t* As = gsm + (i & 1) * 6912;
        uint32_t* Bs = As + 4608;

        if (i + 1 < NT) {
            int kn = (i + 1) * 32;
#pragma unroll
            for (int j = 0; j < 4; j++)
                pa[j] = *(const uint4*)&A[(size_t)(m0 + lr + j * 32) * lda + kn + lc];
#pragma unroll
            for (int j = 0; j < 2; j++)
                pb[j] = *(const uint4*)&B[(size_t)(n0 + lr + j * 32) * ldb + kn + lc];
        }

#pragma unroll
        for (int ks2 = 0; ks2 < 2; ks2++) {
            uint4 alo[2], ahi[2], bv[4];
#pragma unroll
            for (int mt = 0; mt < 2; mt++) {
                int rb = wm + mt * 16;
                alo[mt] = *(const uint4*)&As[(rb + g) * GPAD + c * 8 + ks2 * 4];
                ahi[mt] = *(const uint4*)&As[(rb + g + 8) * GPAD + c * 8 + ks2 * 4];
            }
#pragma unroll
            for (int nt = 0; nt < 4; nt++)
                bv[nt] = *(const uint4*)&Bs[(wn + nt * 8 + g) * GPAD + c * 8 + ks2 * 4];

#pragma unroll
            for (int mt = 0; mt < 2; mt++) {
                uint32_t a0[4] = {alo[mt].x, ahi[mt].x, alo[mt].y, ahi[mt].y};
                uint32_t a1[4] = {alo[mt].z, ahi[mt].z, alo[mt].w, ahi[mt].w};
#pragma unroll
                for (int nt = 0; nt < 4; nt++) {
                    uint32_t b0[2] = {bv[nt].x, bv[nt].y};
                    uint32_t b1[2] = {bv[nt].z, bv[nt].w};
                    mma_tf32(acc[mt][nt], a0, b0);
                    mma_tf32(acc[mt][nt], a1, b1);
                }
            }
        }

        if (i + 1 < NT) {
            uint32_t* Asn = gsm + ((i + 1) & 1) * 6912;
            uint32_t* Bsn = Asn + 4608;
#pragma unroll
            for (int j = 0; j < 4; j++)
                *(uint4*)&Asn[(lr + j * 32) * GPAD + lc] = pa[j];
#pragma unroll
            for (int j = 0; j < 2; j++)
                *(uint4*)&Bsn[(lr + j * 32) * GPAD + lc] = pb[j];
        }
    }

#pragma unroll
    for (int mt = 0; mt < 2; mt++) {
        int r0 = m0 + wm + mt * 16 + g;
#pragma unroll
        for (int nt = 0; nt < 4; nt++) {
            int n = n0 + wn + nt * 8 + 2 * c;
            if (MODE == 0 || MODE == 3) {
                float* C = (float*)Cout;
                float2 v0 = make_float2(acc[mt][nt][0], acc[mt][nt][1]);
                float2 v1 = make_float2(acc[mt][nt][2], acc[mt][nt][3]);
                if (MODE == 3) {
                    float b0 = bias[n], b1 = bias[n + 1];
                    v0.x += b0; v0.y += b1;
                    v1.x += b0; v1.y += b1;
                }
                *(float2*)&C[(size_t)r0 * ldc + n] = v0;
                *(float2*)&C[(size_t)(r0 + 8) * ldc + n] = v1;
            } else {
                uint32_t* C = (uint32_t*)Cout;
                int hb = n & ~31;
                int d0 = n & 31, d1 = d0 + 1;
                int p0, p1;
                if (MODE == 1) { p0 = (d0 & 3) * 8 + (d0 >> 2); p1 = (d1 & 3) * 8 + (d1 >> 2); }
                else           { p0 = (d0 & 7) * 4 + (d0 >> 3); p1 = (d1 & 7) * 4 + (d1 >> 3); }
                C[(size_t)r0 * ldc + hb + p0] = f2tf32(acc[mt][nt][0]);
                C[(size_t)r0 * ldc + hb + p1] = f2tf32(acc[mt][nt][1]);
                C[(size_t)(r0 + 8) * ldc + hb + p0] = f2tf32(acc[mt][nt][2]);
                C[(size_t)(r0 + 8) * ldc + hb + p1] = f2tf32(acc[mt][nt][3]);
            }
        }
    }
}

__global__ void __launch_bounds__(256) gemm_q_kernel() {
    gemm_body<0>(g_xt, HALF, g_wt, HALF, g_q, HALF, nullptr, HALF);
}
__global__ void __launch_bounds__(256) gemm_k_kernel() {
    gemm_body<1>(g_xt, HALF, g_wt + 512 * HALF, HALF, g_k, HALF, nullptr, HALF);
}
__global__ void __launch_bounds__(256) gemm_v_kernel() {
    gemm_body<2>(g_xt, HALF, g_wt + 1024 * HALF, HALF, g_v, HALF, nullptr, HALF);
}
__global__ void __launch_bounds__(256) proj_gemm_kernel(
    const float* __restrict__ bo, float* __restrict__ out) {
    gemm_body<3>(g_at, HALF, g_wt + 1536 * HALF, HALF, out, EMB, bo, HALF);
}

// =====================   Flash attention   =================================
// CTA = 128 q x 1 head, 128 thr (4 warps x 32 q). 64-key tiles, double-buffered.
// K smem: perm rows pad 36 (B-frags via LDS.128). V smem: d-perm rows pad 40
// (B-frags via LDS.128). P smem: interleaved (h in low bit) -> A-frags LDS.128.
// Smem words: K 2*2304, V 2*2560, P 4*2304  => 75776 bytes.
__global__ void __launch_bounds__(128) attn_kernel()
{
    extern __shared__ uint32_t sm_[];
    uint32_t* Pw0 = sm_ + 9728;

    const int t = threadIdx.x;
    const int lane = t & 31;
    const int w = t >> 5;
    const int g = lane >> 2;
    const int c = lane & 3;
    const int h = blockIdx.y;
    const int q0 = blockIdx.x * 128 + w * 32;
    uint32_t* Pw = Pw0 + w * 2304;

    // Q fragments; scale = (1/8)*log2(e) folded in
    const float QS = 0.125f * 1.4426950408889634f;
    uint32_t qa[2][4][4];
#pragma unroll
    for (int mt = 0; mt < 2; mt++) {
        const float* qb = &g_q[(size_t)(q0 + mt * 16) * HALF + h * DH];
#pragma unroll
        for (int ks = 0; ks < 4; ks++) {
            int kk = ks * 8;
            qa[mt][ks][0] = f2tf32(QS * qb[(size_t)g * HALF + kk + c]);
            qa[mt][ks][1] = f2tf32(QS * qb[(size_t)(g + 8) * HALF + kk + c]);
            qa[mt][ks][2] = f2tf32(QS * qb[(size_t)g * HALF + kk + c + 4]);
            qa[mt][ks][3] = f2tf32(QS * qb[(size_t)(g + 8) * HALF + kk + c + 4]);
        }
    }

    float l[2][2] = {};
    float o[2][4][4] = {};

    const int lr = t >> 3;        // 0..15
    const int q8 = t & 7;
    // loader slots: slot = t + i*128 -> r = slot>>3 (0..63), q = slot&7
    uint4 pk[4], pv[4];
#pragma unroll
    for (int i = 0; i < 4; i++) {
        int slot = t + i * 128;
        int r = slot >> 3, qq = slot & 7;
        pk[i] = *(const uint4*)&g_k[(size_t)r * HALF + h * DH + qq * 4];
        pv[i] = *(const uint4*)&g_v[(size_t)r * HALF + h * DH + qq * 4];
    }
    (void)lr; (void)q8;

    // stage tile 0 -> buf 0
#pragma unroll
    for (int i = 0; i < 4; i++) {
        int slot = t + i * 128;
        int r = slot >> 3, qq = slot & 7;
        *(uint4*)&sm_[r * 36 + qq * 4] = pk[i];
        *(uint4*)&sm_[4608 + r * 40 + qq * 4] = pv[i];
    }

    const uint32_t FULL = 0xffffffffu;
    const int NT = S_LEN / 64;
    const int px0 = (c & 1) * 8 + (c & 2);   // P write col offset for even k
    const int px1 = px0 + 4;                  // for odd k

    for (int ti = 0; ti < NT; ti++) {
        __syncthreads();
        const uint32_t* Kb = sm_ + (ti & 1) * 2304;
        const uint32_t* Vb = sm_ + 4608 + (ti & 1) * 2560;

        if (ti + 1 < NT) {
            int kt = (ti + 1) * 64;
#pragma unroll
            for (int i = 0; i < 4; i++) {
                int slot = t + i * 128;
                int r = kt + (slot >> 3), qq = slot & 7;
                pk[i] = *(const uint4*)&g_k[(size_t)r * HALF + h * DH + qq * 4];
                pv[i] = *(const uint4*)&g_v[(size_t)r * HALF + h * DH + qq * 4];
            }
        }

        // S = Q K^T (32 x 64 per warp)
        float s[2][8][4] = {};
#pragma unroll
        for (int ks2 = 0; ks2 < 2; ks2++) {
#pragma unroll
            for (int nt = 0; nt < 8; nt++) {
                uint4 kb = *(const uint4*)&Kb[(nt * 8 + g) * 36 + c * 8 + ks2 * 4];
                uint32_t b0[2] = {kb.x, kb.y};
                uint32_t b1[2] = {kb.z, kb.w};
                mma_tf32(s[0][nt], qa[0][2 * ks2], b0);
                mma_tf32(s[0][nt], qa[0][2 * ks2 + 1], b1);
                mma_tf32(s[1][nt], qa[1][2 * ks2], b0);
                mma_tf32(s[1][nt], qa[1][2 * ks2 + 1], b1);
            }
        }

        // p = exp2(s); accumulate l; stage P into interleaved smem
#pragma unroll
        for (int mt = 0; mt < 2; mt++) {
            uint32_t* pr = &Pw[(mt * 8 + g) * 144];
#pragma unroll
            for (int nt = 0; nt < 8; nt++) {
                float p0 = ex2(s[mt][nt][0]);
                float p1 = ex2(s[mt][nt][1]);
                float p2 = ex2(s[mt][nt][2]);
                float p3 = ex2(s[mt][nt][3]);
                l[mt][0] += p0 + p1;
                l[mt][1] += p2 + p3;
                uint2 w02 = make_uint2(f2tf32(p0), f2tf32(p2));  // (row g, row g+8)
                uint2 w13 = make_uint2(f2tf32(p1), f2tf32(p3));
                *(uint2*)&pr[nt * 16 + px0] = w02;
                *(uint2*)&pr[nt * 16 + px1] = w13;
            }
        }
        __syncwarp();

        // O += P V
#pragma unroll
        for (int k8 = 0; k8 < 8; k8++) {
            int kk = k8 * 8;
            uint4 v0 = *(const uint4*)&Vb[(kk + c) * 40 + g * 4];
            uint4 v1 = *(const uint4*)&Vb[(kk + c + 4) * 40 + g * 4];
            uint32_t b[4][2] = {{v0.x, v1.x}, {v0.y, v1.y}, {v0.z, v1.z}, {v0.w, v1.w}};
#pragma unroll
            for (int mt = 0; mt < 2; mt++) {
                uint4 av = *(const uint4*)&Pw[(mt * 8 + g) * 144 + k8 * 16 + c * 4];
                uint32_t a[4] = {av.x, av.y, av.z, av.w};
#pragma unroll
                for (int nt = 0; nt < 4; nt++)
                    mma_tf32(o[mt][nt], a, b[nt]);
            }
        }
        __syncwarp();

        if (ti + 1 < NT) {
            uint32_t* Kn = sm_ + ((ti + 1) & 1) * 2304;
            uint32_t* Vn = sm_ + 4608 + ((ti + 1) & 1) * 2560;
#pragma unroll
            for (int i = 0; i < 4; i++) {
                int slot = t + i * 128;
                int r = slot >> 3, qq = slot & 7;
                *(uint4*)&Kn[r * 36 + qq * 4] = pk[i];
                *(uint4*)&Vn[r * 40 + qq * 4] = pv[i];
            }
        }
    }

    // reduce l across quad, normalize, write g_at in GEMM-A perm (tf32)
#pragma unroll
    for (int mt = 0; mt < 2; mt++) {
        l[mt][0] += __shfl_xor_sync(FULL, l[mt][0], 1);
        l[mt][0] += __shfl_xor_sync(FULL, l[mt][0], 2);
        l[mt][1] += __shfl_xor_sync(FULL, l[mt][1], 1);
        l[mt][1] += __shfl_xor_sync(FULL, l[mt][1], 2);
        float il0 = 1.0f / l[mt][0], il1 = 1.0f / l[mt][1];
        int r0 = q0 + mt * 16 + g;
#pragma unroll
        for (int nt = 0; nt < 4; nt++) {
            int d0 = nt * 8 + 2 * c, d1 = d0 + 1;
            int p0 = (d0 & 3) * 8 + (d0 >> 2);
            int p1 = (d1 & 3) * 8 + (d1 >> 2);
            uint32_t* ob = &g_at[(size_t)r0 * HALF + h * DH];
            ob[p0] = f2tf32(o[mt][nt][0] * il0);
            ob[p1] = f2tf32(o[mt][nt][1] * il0);
            uint32_t* ob1 = &g_at[(size_t)(r0 + 8) * HALF + h * DH];
            ob1[p0] = f2tf32(o[mt][nt][2] * il1);
            ob1[p1] = f2tf32(o[mt][nt][3] * il1);
        }
    }
}

extern "C" void kernel_launch(void* const* d_in, const int* in_sizes, int n_in,
                              void* d_out, int out_size)
{
    const float* x  = (const float*)d_in[0];
    const float* Wq = (const float*)d_in[1];
    const float* Wk = (const float*)d_in[2];
    const float* Wv = (const float*)d_in[3];
    const float* Wo = (const float*)d_in[4];
    const float* bo = (const float*)d_in[5];
    float* out = (float*)d_out;

    const int GEMM_SMEM = 2 * (128 + 64) * GPAD * 4;   // 55296 B
    const int ATTN_SMEM = (2 * 2304 + 2 * 2560 + 4 * 2304) * 4;  // 75776 B
    static int attr_done = 0;
    if (!attr_done) {
        cudaFuncSetAttribute(gemm_q_kernel, cudaFuncAttributeMaxDynamicSharedMemorySize, GEMM_SMEM);
        cudaFuncSetAttribute(gemm_k_kernel, cudaFuncAttributeMaxDynamicSharedMemorySize, GEMM_SMEM);
        cudaFuncSetAttribute(gemm_v_kernel, cudaFuncAttributeMaxDynamicSharedMemorySize, GEMM_SMEM);
        cudaFuncSetAttribute(proj_gemm_kernel, cudaFuncAttributeMaxDynamicSharedMemorySize, GEMM_SMEM);
        cudaFuncSetAttribute(attn_kernel, cudaFuncAttributeMaxDynamicSharedMemorySize, ATTN_SMEM);
        attr_done = 1;
    }

    conv_x_kernel<<<2048, 256>>>(x);
    conv_w_kernel<<<1280, 256>>>(Wq, Wk, Wv, Wo);

    dim3 gq(S_LEN / 128, HALF / 64);
    gemm_q_kernel<<<gq, 256, GEMM_SMEM>>>();
    gemm_k_kernel<<<gq, 256, GEMM_SMEM>>>();
    gemm_v_kernel<<<gq, 256, GEMM_SMEM>>>();

    dim3 ga(S_LEN / 128, NHEAD);
    attn_kernel<<<ga, 128, ATTN_SMEM>>>();

    dim3 gp(S_LEN / 128, EMB / 64);
    proj_gemm_kernel<<<gp, 256, GEMM_SMEM>>>(bo, out);
}

// round 7
// speedup vs baseline: 2.2885x; 2.2885x over previous
#include <cuda_runtime.h>
#include <cuda_fp16.h>
#include <cstdint>

#define S_LEN 4096
#define EMB   1024
#define HALF  512
#define NHEAD 16
#define DH    32

// f16 scratch
__device__ __half g_xh [S_LEN * HALF];   // x left half
__device__ __half g_wh [2560 * HALF];    // Wq|Wk|Wv|Wo rows (k-major)
__device__ __half g_qh [S_LEN * HALF];   // Q (scale*log2e folded in)
__device__ __half g_kh [S_LEN * HALF];
__device__ __half g_vh [S_LEN * HALF];
__device__ __half g_ath[S_LEN * HALF];   // attention output

__device__ __forceinline__ uint32_t packh2(float lo, float hi) {
    uint32_t r;
    asm("cvt.rn.f16x2.f32 %0, %1, %2;" : "=r"(r) : "f"(hi), "f"(lo));
    return r;
}
__device__ __forceinline__ uint32_t ex2h2(uint32_t s) {
    uint32_t r;
    asm("ex2.approx.f16x2 %0, %1;" : "=r"(r) : "r"(s));
    return r;
}
__device__ __forceinline__ uint32_t smem_u32(const void* p) {
    uint32_t a;
    asm("{ .reg .u64 t; cvta.to.shared.u64 t, %1; cvt.u32.u64 %0, t; }" : "=r"(a) : "l"(p));
    return a;
}
// m16n8k16 f16 mma, f32 accum.
// A: a0={(g,2c),(g,2c+1)} a1={(g+8,2c),..} a2={(g,2c+8),..} a3={(g+8,2c+8),..}
// B: b0={(2c,g),(2c+1,g)} b1={(2c+8,g),(2c+9,g)}
// C: c0=(g,2c) c1=(g,2c+1) c2=(g+8,2c) c3=(g+8,2c+1)
__device__ __forceinline__ void mma_f16(float* d, const uint32_t* a, uint32_t b0, uint32_t b1) {
    asm volatile(
        "mma.sync.aligned.m16n8k16.row.col.f32.f16.f16.f32 "
        "{%0,%1,%2,%3}, {%4,%5,%6,%7}, {%8,%9}, {%0,%1,%2,%3};"
        : "+f"(d[0]), "+f"(d[1]), "+f"(d[2]), "+f"(d[3])
        : "r"(a[0]), "r"(a[1]), "r"(a[2]), "r"(a[3]), "r"(b0), "r"(b1));
}
__device__ __forceinline__ void ldsm4(uint32_t* r, uint32_t a) {
    asm volatile("ldmatrix.sync.aligned.m8n8.x4.shared.b16 {%0,%1,%2,%3}, [%4];"
        : "=r"(r[0]), "=r"(r[1]), "=r"(r[2]), "=r"(r[3]) : "r"(a));
}
__device__ __forceinline__ void ldsm4t(uint32_t* r, uint32_t a) {
    asm volatile("ldmatrix.sync.aligned.m8n8.x4.trans.shared.b16 {%0,%1,%2,%3}, [%4];"
        : "=r"(r[0]), "=r"(r[1]), "=r"(r[2]), "=r"(r[3]) : "r"(a));
}

// ======================= conversion prologues ==============================
__global__ void __launch_bounds__(256) conv_x_kernel(const float* __restrict__ x)
{
    int idx = blockIdx.x * 256 + threadIdx.x;   // 0..262143
    int r = idx >> 6;
    int c8 = (idx & 63) * 8;
    const float4 v0 = *(const float4*)&x[(size_t)r * EMB + c8];
    const float4 v1 = *(const float4*)&x[(size_t)r * EMB + c8 + 4];
    uint4 o;
    o.x = packh2(v0.x, v0.y); o.y = packh2(v0.z, v0.w);
    o.z = packh2(v1.x, v1.y); o.w = packh2(v1.z, v1.w);
    *(uint4*)&g_xh[(size_t)r * HALF + c8] = o;
}

__global__ void __launch_bounds__(256) conv_w_kernel(
    const float* __restrict__ Wq, const float* __restrict__ Wk,
    const float* __restrict__ Wv, const float* __restrict__ Wo)
{
    int idx = blockIdx.x * 256 + threadIdx.x;   // 0..163839
    int r = idx >> 6;
    int c8 = (idx & 63) * 8;
    const float* src;
    if (r < 512)       src = Wq + (size_t)r * HALF;
    else if (r < 1024) src = Wk + (size_t)(r - 512) * HALF;
    else if (r < 1536) src = Wv + (size_t)(r - 1024) * HALF;
    else               src = Wo + (size_t)(r - 1536) * HALF;
    const float4 v0 = *(const float4*)&src[c8];
    const float4 v1 = *(const float4*)&src[c8 + 4];
    uint4 o;
    o.x = packh2(v0.x, v0.y); o.y = packh2(v0.z, v0.w);
    o.z = packh2(v1.x, v1.y); o.w = packh2(v1.z, v1.w);
    *(uint4*)&g_wh[(size_t)r * HALF + c8] = o;
}

// ======================= f16 GEMM ==========================================
// C[m][n] = sum_k A[m][k]*B[n][k]. CTA 128x64, BK=32, 256 thr (8 warps),
// warp tile 32x32. Swizzled 64B smem rows, ldmatrix frags, double-buffered.
// MODE 0/1/2: write half2 (scale folded), MODE 3: float + bias.
template <int MODE>
__device__ __forceinline__ void gemm_h(
    const __half* __restrict__ Ag, const __half* __restrict__ Bg,
    void* __restrict__ Cout, int ldc, const float* __restrict__ bias, float scale)
{
    __shared__ __align__(16) uint8_t sA[2][8192];
    __shared__ __align__(16) uint8_t sB[2][4096];

    const int t = threadIdx.x;
    const int lane = t & 31;
    const int w = t >> 5;
    const int wm = (w & 3) * 32;
    const int wn = (w >> 2) * 32;
    const int g = lane >> 2;
    const int c = lane & 3;
    const int grp = lane >> 3;
    const int m0 = blockIdx.x * 128;
    const int n0 = blockIdx.y * 64;

    // ldmatrix address components
    const int arow0 = (lane & 7) + 8 * (grp & 1);     // A: row += 8*(grp&1)
    const int ajb = grp >> 1;                          // A: chunk = 2kc + (grp>>1)
    const int asw = (arow0 >> 1) & 3;
    const int brow0 = (lane & 7) + 8 * (grp >> 1);    // B: row += 8*(grp>>1)
    const int bjb = grp & 1;
    const int bsw = (brow0 >> 1) & 3;

    // loader: A 512 chunk-slots (2/thread), B 256 (1/thread)
    const int ar[2] = {t >> 2, (t + 256) >> 2};
    const int ac = t & 3;
    const int br = t >> 2;

    uint4 pa[2], pb;
#pragma unroll
    for (int i = 0; i < 2; i++)
        pa[i] = *(const uint4*)((const uint8_t*)Ag + (size_t)(m0 + ar[i]) * 1024 + ac * 16);
    pb = *(const uint4*)((const uint8_t*)Bg + (size_t)(n0 + br) * 1024 + ac * 16);

    {
#pragma unroll
        for (int i = 0; i < 2; i++)
            *(uint4*)(sA[0] + ar[i] * 64 + ((ac ^ ((ar[i] >> 1) & 3)) << 4)) = pa[i];
        *(uint4*)(sB[0] + br * 64 + ((ac ^ ((br >> 1) & 3)) << 4)) = pb;
    }

    float acc[2][4][4] = {};

#pragma unroll 1
    for (int i = 0; i < 16; i++) {
        __syncthreads();
        const int b = i & 1;
        if (i < 15) {
            const int k0 = (i + 1) * 32;
#pragma unroll
            for (int j = 0; j < 2; j++)
                pa[j] = *(const uint4*)((const uint8_t*)Ag + (size_t)(m0 + ar[j]) * 1024 + k0 * 2 + ac * 16);
            pb = *(const uint4*)((const uint8_t*)Bg + (size_t)(n0 + br) * 1024 + k0 * 2 + ac * 16);
        }
        const uint32_t abase = smem_u32(sA[b]);
        const uint32_t bbase = smem_u32(sB[b]);
#pragma unroll
        for (int kc = 0; kc < 2; kc++) {
            uint32_t av[2][4], bv[2][4];
#pragma unroll
            for (int mt = 0; mt < 2; mt++)
                ldsm4(av[mt], abase + (wm + mt * 16 + arow0) * 64 + (((2 * kc + ajb) ^ asw) << 4));
#pragma unroll
            for (int np = 0; np < 2; np++)
                ldsm4(bv[np], bbase + (wn + np * 16 + brow0) * 64 + (((2 * kc + bjb) ^ bsw) << 4));
#pragma unroll
            for (int mt = 0; mt < 2; mt++)
#pragma unroll
                for (int np = 0; np < 2; np++) {
                    mma_f16(acc[mt][2 * np], av[mt], bv[np][0], bv[np][1]);
                    mma_f16(acc[mt][2 * np + 1], av[mt], bv[np][2], bv[np][3]);
                }
        }
        if (i < 15) {
            uint8_t* dA = sA[b ^ 1];
            uint8_t* dB = sB[b ^ 1];
#pragma unroll
            for (int j = 0; j < 2; j++)
                *(uint4*)(dA + ar[j] * 64 + ((ac ^ ((ar[j] >> 1) & 3)) << 4)) = pa[j];
            *(uint4*)(dB + br * 64 + ((ac ^ ((br >> 1) & 3)) << 4)) = pb;
        }
    }

#pragma unroll
    for (int mt = 0; mt < 2; mt++) {
        const int r0 = m0 + wm + mt * 16 + g;
#pragma unroll
        for (int np = 0; np < 2; np++)
#pragma unroll
            for (int hf = 0; hf < 2; hf++) {
                const int col = n0 + wn + np * 16 + hf * 8 + 2 * c;
                const float* a = acc[mt][2 * np + hf];
                if (MODE == 3) {
                    float* C = (float*)Cout;
                    const float b0 = bias[col], b1 = bias[col + 1];
                    *(float2*)&C[(size_t)r0 * ldc + col] = make_float2(a[0] + b0, a[1] + b1);
                    *(float2*)&C[(size_t)(r0 + 8) * ldc + col] = make_float2(a[2] + b0, a[3] + b1);
                } else {
                    uint32_t* C = (uint32_t*)Cout;
                    C[(size_t)r0 * (ldc / 2) + col / 2] = packh2(a[0] * scale, a[1] * scale);
                    C[(size_t)(r0 + 8) * (ldc / 2) + col / 2] = packh2(a[2] * scale, a[3] * scale);
                }
            }
    }
}

__global__ void __launch_bounds__(256) qkv_h_kernel()
{
    const int z = blockIdx.z;
    const float QS = 0.125f * 1.4426950408889634f;
    const __half* B = g_wh + (size_t)z * 512 * HALF;
    void* C = (z == 0) ? (void*)g_qh : (z == 1) ? (void*)g_kh : (void*)g_vh;
    gemm_h<0>(g_xh, B, C, HALF, nullptr, (z == 0) ? QS : 1.0f);
}

__global__ void __launch_bounds__(256) proj_h_kernel(
    const float* __restrict__ bo, float* __restrict__ out)
{
    gemm_h<3>(g_ath, g_wh + (size_t)1536 * HALF, out, EMB, bo, 1.0f);
}

// ======================= flash attention (f16) =============================
// CTA = 128 q x 1 head, 128 thr (4 warps x 32 q). 64-key tiles, double-buffered.
// QK^T C-frag -> (cvt+ex2 f16x2) -> PV A-frag in registers. l via ones-mma.
__global__ void __launch_bounds__(128) attn_kernel()
{
    __shared__ __align__(16) uint8_t sK[2][4096];
    __shared__ __align__(16) uint8_t sV[2][4096];

    const int t = threadIdx.x;
    const int lane = t & 31;
    const int w = t >> 5;
    const int g = lane >> 2;
    const int c = lane & 3;
    const int grp = lane >> 3;
    const int h = blockIdx.y;
    const int q0 = blockIdx.x * 128 + w * 32;

    // K (B-operand) ldmatrix comps
    const int krow0 = (lane & 7) + 8 * (grp >> 1);
    const int kjb = grp & 1;
    const int ksw = (krow0 >> 1) & 3;
    // V (trans B-operand) comps
    const int vrow0 = (lane & 7) + 8 * (grp & 1);
    const int vjb = grp >> 1;
    const int vsw = (vrow0 >> 1) & 3;

    // Q fragments (f16 pairs straight from gmem; scale already folded)
    uint32_t qa[2][2][4];
#pragma unroll
    for (int mt = 0; mt < 2; mt++) {
        const uint32_t* r0p = (const uint32_t*)g_qh + (size_t)(q0 + mt * 16 + g) * 256 + h * 16;
        const uint32_t* r8p = r0p + 8 * 256;
#pragma unroll
        for (int kc = 0; kc < 2; kc++) {
            qa[mt][kc][0] = r0p[8 * kc + c];
            qa[mt][kc][1] = r8p[8 * kc + c];
            qa[mt][kc][2] = r0p[8 * kc + c + 4];
            qa[mt][kc][3] = r8p[8 * kc + c + 4];
        }
    }

    float o[2][4][4] = {};
    float lacc[2][4] = {};
    const uint32_t ONE2 = 0x3C003C00u;

    const uint8_t* Kh = (const uint8_t*)(g_kh + h * DH);
    const uint8_t* Vh = (const uint8_t*)(g_vh + h * DH);

    // loader: 256 chunk-slots per matrix, 2 per thread
    const int lr[2] = {t >> 2, (t + 128) >> 2};
    const int lc = t & 3;

    uint4 pk[2], pv[2];
#pragma unroll
    for (int i = 0; i < 2; i++) {
        pk[i] = *(const uint4*)(Kh + (size_t)lr[i] * 1024 + lc * 16);
        pv[i] = *(const uint4*)(Vh + (size_t)lr[i] * 1024 + lc * 16);
    }
#pragma unroll
    for (int i = 0; i < 2; i++) {
        const int off = lr[i] * 64 + ((lc ^ ((lr[i] >> 1) & 3)) << 4);
        *(uint4*)(sK[0] + off) = pk[i];
        *(uint4*)(sV[0] + off) = pv[i];
    }

#pragma unroll 1
    for (int ti = 0; ti < S_LEN / 64; ti++) {
        __syncthreads();
        const int b = ti & 1;
        if (ti < S_LEN / 64 - 1) {
            const size_t kt = (size_t)(ti + 1) * 64;
#pragma unroll
            for (int i = 0; i < 2; i++) {
                pk[i] = *(const uint4*)(Kh + (kt + lr[i]) * 1024 + lc * 16);
                pv[i] = *(const uint4*)(Vh + (kt + lr[i]) * 1024 + lc * 16);
            }
        }
        const uint32_t kb = smem_u32(sK[b]);
        const uint32_t vb = smem_u32(sV[b]);

        // S = Q K^T : 32q x 64keys per warp
        float s[2][8][4] = {};
#pragma unroll
        for (int kc = 0; kc < 2; kc++)
#pragma unroll
            for (int ntp = 0; ntp < 4; ntp++) {
                uint32_t kv[4];
                ldsm4(kv, kb + (ntp * 16 + krow0) * 64 + (((2 * kc + kjb) ^ ksw) << 4));
#pragma unroll
                for (int mt = 0; mt < 2; mt++) {
                    mma_f16(s[mt][2 * ntp], qa[mt][kc], kv[0], kv[1]);
                    mma_f16(s[mt][2 * ntp + 1], qa[mt][kc], kv[2], kv[3]);
                }
            }

        // P = exp2(S) as f16x2 pairs (C-frag -> A-frag, in registers)
        uint32_t p[2][8][2];
#pragma unroll
        for (int mt = 0; mt < 2; mt++)
#pragma unroll
            for (int nt = 0; nt < 8; nt++) {
                p[mt][nt][0] = ex2h2(packh2(s[mt][nt][0], s[mt][nt][1]));
                p[mt][nt][1] = ex2h2(packh2(s[mt][nt][2], s[mt][nt][3]));
            }

        // O += P V ; l += P 1
#pragma unroll
        for (int kk = 0; kk < 4; kk++) {
            uint32_t v0[4], v1[4];
            const uint32_t vrow = vb + (kk * 16 + vrow0) * 64;
            ldsm4t(v0, vrow + (((0 + vjb) ^ vsw) << 4));
            ldsm4t(v1, vrow + (((2 + vjb) ^ vsw) << 4));
#pragma unroll
            for (int mt = 0; mt < 2; mt++) {
                uint32_t a[4] = {p[mt][2 * kk][0], p[mt][2 * kk][1],
                                 p[mt][2 * kk + 1][0], p[mt][2 * kk + 1][1]};
                mma_f16(o[mt][0], a, v0[0], v0[1]);
                mma_f16(o[mt][1], a, v0[2], v0[3]);
                mma_f16(o[mt][2], a, v1[0], v1[1]);
                mma_f16(o[mt][3], a, v1[2], v1[3]);
                mma_f16(lacc[mt], a, ONE2, ONE2);
            }
        }

        if (ti < S_LEN / 64 - 1) {
            uint8_t* dK = sK[b ^ 1];
            uint8_t* dV = sV[b ^ 1];
#pragma unroll
            for (int i = 0; i < 2; i++) {
                const int off = lr[i] * 64 + ((lc ^ ((lr[i] >> 1) & 3)) << 4);
                *(uint4*)(dK + off) = pk[i];
                *(uint4*)(dV + off) = pv[i];
            }
        }
    }

    // normalize + write f16
#pragma unroll
    for (int mt = 0; mt < 2; mt++) {
        const float il0 = 1.0f / lacc[mt][0];
        const float il1 = 1.0f / lacc[mt][2];
        const int r0 = q0 + mt * 16 + g;
        uint32_t* d0 = (uint32_t*)g_ath + (size_t)r0 * 256 + h * 16;
        uint32_t* d1 = d0 + 8 * 256;
#pragma unroll
        for (int nt = 0; nt < 4; nt++) {
            d0[nt * 4 + c] = packh2(o[mt][nt][0] * il0, o[mt][nt][1] * il0);
            d1[nt * 4 + c] = packh2(o[mt][nt][2] * il1, o[mt][nt][3] * il1);
        }
    }
}

extern "C" void kernel_launch(void* const* d_in, const int* in_sizes, int n_in,
                              void* d_out, int out_size)
{
    const float* x  = (const float*)d_in[0];
    const float* Wq = (const float*)d_in[1];
    const float* Wk = (const float*)d_in[2];
    const float* Wv = (const float*)d_in[3];
    const float* Wo = (const float*)d_in[4];
    const float* bo = (const float*)d_in[5];
    float* out = (float*)d_out;

    conv_x_kernel<<<1024, 256>>>(x);
    conv_w_kernel<<<640, 256>>>(Wq, Wk, Wv, Wo);

    dim3 gq(S_LEN / 128, HALF / 64, 3);
    qkv_h_kernel<<<gq, 256>>>();

    dim3 ga(S_LEN / 128, NHEAD);
    attn_kernel<<<ga, 128>>>();

    dim3 gp(S_LEN / 128, EMB / 64);
    proj_h_kernel<<<gp, 256>>>(bo, out);
}

// round 8
// speedup vs baseline: 2.3700x; 1.0356x over previous
#include <cuda_runtime.h>
#include <cuda_fp16.h>
#include <cstdint>

#define S_LEN 4096
#define EMB   1024
#define HALF  512
#define NHEAD 16
#define DH    32

// f16 scratch
__device__ __half g_xh [S_LEN * HALF];   // x left half
__device__ __half g_wh [2560 * HALF];    // Wq|Wk|Wv|Wo rows (k-major)
__device__ __half g_qh [S_LEN * HALF];   // Q (scale*log2e folded in)
__device__ __half g_kh [S_LEN * HALF];
__device__ __half g_vh [S_LEN * HALF];
__device__ __half g_ath[S_LEN * HALF];   // attention output

__device__ __forceinline__ uint32_t packh2(float lo, float hi) {
    uint32_t r;
    asm("cvt.rn.f16x2.f32 %0, %1, %2;" : "=r"(r) : "f"(hi), "f"(lo));
    return r;
}
__device__ __forceinline__ uint32_t ex2h2(uint32_t s) {
    uint32_t r;
    asm("ex2.approx.f16x2 %0, %1;" : "=r"(r) : "r"(s));
    return r;
}
__device__ __forceinline__ uint32_t smem_u32(const void* p) {
    uint32_t a;
    asm("{ .reg .u64 t; cvta.to.shared.u64 t, %1; cvt.u32.u64 %0, t; }" : "=r"(a) : "l"(p));
    return a;
}
// m16n8k16 f16 mma, f32 accum.
__device__ __forceinline__ void mma_f16(float* d, const uint32_t* a, uint32_t b0, uint32_t b1) {
    asm volatile(
        "mma.sync.aligned.m16n8k16.row.col.f32.f16.f16.f32 "
        "{%0,%1,%2,%3}, {%4,%5,%6,%7}, {%8,%9}, {%0,%1,%2,%3};"
        : "+f"(d[0]), "+f"(d[1]), "+f"(d[2]), "+f"(d[3])
        : "r"(a[0]), "r"(a[1]), "r"(a[2]), "r"(a[3]), "r"(b0), "r"(b1));
}
__device__ __forceinline__ void ldsm4(uint32_t* r, uint32_t a) {
    asm volatile("ldmatrix.sync.aligned.m8n8.x4.shared.b16 {%0,%1,%2,%3}, [%4];"
        : "=r"(r[0]), "=r"(r[1]), "=r"(r[2]), "=r"(r[3]) : "r"(a));
}
__device__ __forceinline__ void ldsm4t(uint32_t* r, uint32_t a) {
    asm volatile("ldmatrix.sync.aligned.m8n8.x4.trans.shared.b16 {%0,%1,%2,%3}, [%4];"
        : "=r"(r[0]), "=r"(r[1]), "=r"(r[2]), "=r"(r[3]) : "r"(a));
}

// ======================= conversion prologues ==============================
__global__ void __launch_bounds__(256) conv_x_kernel(const float* __restrict__ x)
{
    int idx = blockIdx.x * 256 + threadIdx.x;
    int r = idx >> 6;
    int c8 = (idx & 63) * 8;
    const float4 v0 = *(const float4*)&x[(size_t)r * EMB + c8];
    const float4 v1 = *(const float4*)&x[(size_t)r * EMB + c8 + 4];
    uint4 o;
    o.x = packh2(v0.x, v0.y); o.y = packh2(v0.z, v0.w);
    o.z = packh2(v1.x, v1.y); o.w = packh2(v1.z, v1.w);
    *(uint4*)&g_xh[(size_t)r * HALF + c8] = o;
}

__global__ void __launch_bounds__(256) conv_w_kernel(
    const float* __restrict__ Wq, const float* __restrict__ Wk,
    const float* __restrict__ Wv, const float* __restrict__ Wo)
{
    int idx = blockIdx.x * 256 + threadIdx.x;
    int r = idx >> 6;
    int c8 = (idx & 63) * 8;
    const float* src;
    if (r < 512)       src = Wq + (size_t)r * HALF;
    else if (r < 1024) src = Wk + (size_t)(r - 512) * HALF;
    else if (r < 1536) src = Wv + (size_t)(r - 1024) * HALF;
    else               src = Wo + (size_t)(r - 1536) * HALF;
    const float4 v0 = *(const float4*)&src[c8];
    const float4 v1 = *(const float4*)&src[c8 + 4];
    uint4 o;
    o.x = packh2(v0.x, v0.y); o.y = packh2(v0.z, v0.w);
    o.z = packh2(v1.x, v1.y); o.w = packh2(v1.z, v1.w);
    *(uint4*)&g_wh[(size_t)r * HALF + c8] = o;
}

// ======================= f16 GEMM ==========================================
// CTA 128x64, BK=32, 256 thr (8 warps), warp tile 32x32. Swizzled 64B rows,
// ldmatrix frags, double-buffered. MODE 0: half2 out (scaled). 3: float+bias.
template <int MODE>
__device__ __forceinline__ void gemm_h(
    const __half* __restrict__ Ag, const __half* __restrict__ Bg,
    void* __restrict__ Cout, int ldc, const float* __restrict__ bias, float scale)
{
    __shared__ __align__(16) uint8_t sA[2][8192];
    __shared__ __align__(16) uint8_t sB[2][4096];

    const int t = threadIdx.x;
    const int lane = t & 31;
    const int w = t >> 5;
    const int wm = (w & 3) * 32;
    const int wn = (w >> 2) * 32;
    const int g = lane >> 2;
    const int c = lane & 3;
    const int grp = lane >> 3;
    const int m0 = blockIdx.x * 128;
    const int n0 = blockIdx.y * 64;

    const int arow0 = (lane & 7) + 8 * (grp & 1);
    const int ajb = grp >> 1;
    const int asw = (arow0 >> 1) & 3;
    const int brow0 = (lane & 7) + 8 * (grp >> 1);
    const int bjb = grp & 1;
    const int bsw = (brow0 >> 1) & 3;

    const int ar[2] = {t >> 2, (t + 256) >> 2};
    const int ac = t & 3;
    const int br = t >> 2;

    uint4 pa[2], pb;
#pragma unroll
    for (int i = 0; i < 2; i++)
        pa[i] = *(const uint4*)((const uint8_t*)Ag + (size_t)(m0 + ar[i]) * 1024 + ac * 16);
    pb = *(const uint4*)((const uint8_t*)Bg + (size_t)(n0 + br) * 1024 + ac * 16);

    {
#pragma unroll
        for (int i = 0; i < 2; i++)
            *(uint4*)(sA[0] + ar[i] * 64 + ((ac ^ ((ar[i] >> 1) & 3)) << 4)) = pa[i];
        *(uint4*)(sB[0] + br * 64 + ((ac ^ ((br >> 1) & 3)) << 4)) = pb;
    }

    float acc[2][4][4] = {};

#pragma unroll 1
    for (int i = 0; i < 16; i++) {
        __syncthreads();
        const int b = i & 1;
        if (i < 15) {
            const int k0 = (i + 1) * 32;
#pragma unroll
            for (int j = 0; j < 2; j++)
                pa[j] = *(const uint4*)((const uint8_t*)Ag + (size_t)(m0 + ar[j]) * 1024 + k0 * 2 + ac * 16);
            pb = *(const uint4*)((const uint8_t*)Bg + (size_t)(n0 + br) * 1024 + k0 * 2 + ac * 16);
        }
        const uint32_t abase = smem_u32(sA[b]);
        const uint32_t bbase = smem_u32(sB[b]);
#pragma unroll
        for (int kc = 0; kc < 2; kc++) {
            uint32_t av[2][4], bv[2][4];
#pragma unroll
            for (int mt = 0; mt < 2; mt++)
                ldsm4(av[mt], abase + (wm + mt * 16 + arow0) * 64 + (((2 * kc + ajb) ^ asw) << 4));
#pragma unroll
            for (int np = 0; np < 2; np++)
                ldsm4(bv[np], bbase + (wn + np * 16 + brow0) * 64 + (((2 * kc + bjb) ^ bsw) << 4));
#pragma unroll
            for (int mt = 0; mt < 2; mt++)
#pragma unroll
                for (int np = 0; np < 2; np++) {
                    mma_f16(acc[mt][2 * np], av[mt], bv[np][0], bv[np][1]);
                    mma_f16(acc[mt][2 * np + 1], av[mt], bv[np][2], bv[np][3]);
                }
        }
        if (i < 15) {
            uint8_t* dA = sA[b ^ 1];
            uint8_t* dB = sB[b ^ 1];
#pragma unroll
            for (int j = 0; j < 2; j++)
                *(uint4*)(dA + ar[j] * 64 + ((ac ^ ((ar[j] >> 1) & 3)) << 4)) = pa[j];
            *(uint4*)(dB + br * 64 + ((ac ^ ((br >> 1) & 3)) << 4)) = pb;
        }
    }

#pragma unroll
    for (int mt = 0; mt < 2; mt++) {
        const int r0 = m0 + wm + mt * 16 + g;
#pragma unroll
        for (int np = 0; np < 2; np++)
#pragma unroll
            for (int hf = 0; hf < 2; hf++) {
                const int col = n0 + wn + np * 16 + hf * 8 + 2 * c;
                const float* a = acc[mt][2 * np + hf];
                if (MODE == 3) {
                    float* C = (float*)Cout;
                    const float b0 = bias[col], b1 = bias[col + 1];
                    *(float2*)&C[(size_t)r0 * ldc + col] = make_float2(a[0] + b0, a[1] + b1);
                    *(float2*)&C[(size_t)(r0 + 8) * ldc + col] = make_float2(a[2] + b0, a[3] + b1);
                } else {
                    uint32_t* C = (uint32_t*)Cout;
                    C[(size_t)r0 * (ldc / 2) + col / 2] = packh2(a[0] * scale, a[1] * scale);
                    C[(size_t)(r0 + 8) * (ldc / 2) + col / 2] = packh2(a[2] * scale, a[3] * scale);
                }
            }
    }
}

__global__ void __launch_bounds__(256) qkv_h_kernel()
{
    const int z = blockIdx.z;
    const float QS = 0.125f * 1.4426950408889634f;
    const __half* B = g_wh + (size_t)z * 512 * HALF;
    void* C = (z == 0) ? (void*)g_qh : (z == 1) ? (void*)g_kh : (void*)g_vh;
    gemm_h<0>(g_xh, B, C, HALF, nullptr, (z == 0) ? QS : 1.0f);
}

__global__ void __launch_bounds__(256) proj_h_kernel(
    const float* __restrict__ bo, float* __restrict__ out)
{
    gemm_h<3>(g_ath, g_wh + (size_t)1536 * HALF, out, EMB, bo, 1.0f);
}

// ======================= flash attention (f16) =============================
// CTA = 128 q x 1 head, 128 thr (4 warps x 32 q). 128-key tiles (two 64-key
// halves, no barrier between), double-buffered. C-frag -> cvt/ex2 -> A-frag
// in registers; l via ones-mma.
__global__ void __launch_bounds__(128) attn_kernel()
{
    __shared__ __align__(16) uint8_t sK[2][8192];
    __shared__ __align__(16) uint8_t sV[2][8192];

    const int t = threadIdx.x;
    const int lane = t & 31;
    const int w = t >> 5;
    const int g = lane >> 2;
    const int c = lane & 3;
    const int grp = lane >> 3;
    const int h = blockIdx.y;
    const int q0 = blockIdx.x * 128 + w * 32;

    const int krow0 = (lane & 7) + 8 * (grp >> 1);
    const int kjb = grp & 1;
    const int ksw = (krow0 >> 1) & 3;
    const int vrow0 = (lane & 7) + 8 * (grp & 1);
    const int vjb = grp >> 1;
    const int vsw = (vrow0 >> 1) & 3;

    // Q fragments (scale folded in)
    uint32_t qa[2][2][4];
#pragma unroll
    for (int mt = 0; mt < 2; mt++) {
        const uint32_t* r0p = (const uint32_t*)g_qh + (size_t)(q0 + mt * 16 + g) * 256 + h * 16;
        const uint32_t* r8p = r0p + 8 * 256;
#pragma unroll
        for (int kc = 0; kc < 2; kc++) {
            qa[mt][kc][0] = r0p[8 * kc + c];
            qa[mt][kc][1] = r8p[8 * kc + c];
            qa[mt][kc][2] = r0p[8 * kc + c + 4];
            qa[mt][kc][3] = r8p[8 * kc + c + 4];
        }
    }

    float o[2][4][4] = {};
    float lacc[2][4] = {};
    const uint32_t ONE2 = 0x3C003C00u;

    const uint8_t* Kh = (const uint8_t*)(g_kh + h * DH);
    const uint8_t* Vh = (const uint8_t*)(g_vh + h * DH);

    // loader: 512 chunk-slots per matrix (128 rows x 4), 4 per thread
    const int lr[4] = {t >> 2, (t + 128) >> 2, (t + 256) >> 2, (t + 384) >> 2};
    const int lc = t & 3;

    uint4 pk[4], pv[4];
#pragma unroll
    for (int i = 0; i < 4; i++) {
        pk[i] = *(const uint4*)(Kh + (size_t)lr[i] * 1024 + lc * 16);
        pv[i] = *(const uint4*)(Vh + (size_t)lr[i] * 1024 + lc * 16);
    }
#pragma unroll
    for (int i = 0; i < 4; i++) {
        const int off = lr[i] * 64 + ((lc ^ ((lr[i] >> 1) & 3)) << 4);
        *(uint4*)(sK[0] + off) = pk[i];
        *(uint4*)(sV[0] + off) = pv[i];
    }

#pragma unroll 1
    for (int ti = 0; ti < S_LEN / 128; ti++) {
        __syncthreads();
        const int b = ti & 1;
        if (ti < S_LEN / 128 - 1) {
            const size_t kt = (size_t)(ti + 1) * 128;
#pragma unroll
            for (int i = 0; i < 4; i++) {
                pk[i] = *(const uint4*)(Kh + (kt + lr[i]) * 1024 + lc * 16);
                pv[i] = *(const uint4*)(Vh + (kt + lr[i]) * 1024 + lc * 16);
            }
        }
        const uint32_t kbase = smem_u32(sK[b]);
        const uint32_t vbase = smem_u32(sV[b]);

#pragma unroll
        for (int hf2 = 0; hf2 < 2; hf2++) {
            const int roff = hf2 * 64;

            // S = Q K^T : 32q x 64keys per warp
            float s[2][8][4] = {};
#pragma unroll
            for (int kc = 0; kc < 2; kc++)
#pragma unroll
                for (int ntp = 0; ntp < 4; ntp++) {
                    uint32_t kv[4];
                    ldsm4(kv, kbase + (roff + ntp * 16 + krow0) * 64 + (((2 * kc + kjb) ^ ksw) << 4));
#pragma unroll
                    for (int mt = 0; mt < 2; mt++) {
                        mma_f16(s[mt][2 * ntp], qa[mt][kc], kv[0], kv[1]);
                        mma_f16(s[mt][2 * ntp + 1], qa[mt][kc], kv[2], kv[3]);
                    }
                }

            // P = exp2(S) as f16x2 (C-frag -> A-frag in registers)
            uint32_t p[2][8][2];
#pragma unroll
            for (int mt = 0; mt < 2; mt++)
#pragma unroll
                for (int nt = 0; nt < 8; nt++) {
                    p[mt][nt][0] = ex2h2(packh2(s[mt][nt][0], s[mt][nt][1]));
                    p[mt][nt][1] = ex2h2(packh2(s[mt][nt][2], s[mt][nt][3]));
                }

            // O += P V ; l += P 1
#pragma unroll
            for (int kk = 0; kk < 4; kk++) {
                uint32_t v0[4], v1[4];
                const uint32_t vrow = vbase + (roff + kk * 16 + vrow0) * 64;
                ldsm4t(v0, vrow + (((0 + vjb) ^ vsw) << 4));
                ldsm4t(v1, vrow + (((2 + vjb) ^ vsw) << 4));
#pragma unroll
                for (int mt = 0; mt < 2; mt++) {
                    uint32_t a[4] = {p[mt][2 * kk][0], p[mt][2 * kk][1],
                                     p[mt][2 * kk + 1][0], p[mt][2 * kk + 1][1]};
                    mma_f16(o[mt][0], a, v0[0], v0[1]);
                    mma_f16(o[mt][1], a, v0[2], v0[3]);
                    mma_f16(o[mt][2], a, v1[0], v1[1]);
                    mma_f16(o[mt][3], a, v1[2], v1[3]);
                    mma_f16(lacc[mt], a, ONE2, ONE2);
                }
            }
        }

        if (ti < S_LEN / 128 - 1) {
            uint8_t* dK = sK[b ^ 1];
            uint8_t* dV = sV[b ^ 1];
#pragma unroll
            for (int i = 0; i < 4; i++) {
                const int off = lr[i] * 64 + ((lc ^ ((lr[i] >> 1) & 3)) << 4);
                *(uint4*)(dK + off) = pk[i];
                *(uint4*)(dV + off) = pv[i];
            }
        }
    }

    // normalize + write f16
#pragma unroll
    for (int mt = 0; mt < 2; mt++) {
        const float il0 = 1.0f / lacc[mt][0];
        const float il1 = 1.0f / lacc[mt][2];
        const int r0 = q0 + mt * 16 + g;
        uint32_t* d0 = (uint32_t*)g_ath + (size_t)r0 * 256 + h * 16;
        uint32_t* d1 = d0 + 8 * 256;
#pragma unroll
        for (int nt = 0; nt < 4; nt++) {
            d0[nt * 4 + c] = packh2(o[mt][nt][0] * il0, o[mt][nt][1] * il0);
            d1[nt * 4 + c] = packh2(o[mt][nt][2] * il1, o[mt][nt][3] * il1);
        }
    }
}

extern "C" void kernel_launch(void* const* d_in, const int* in_sizes, int n_in,
                              void* d_out, int out_size)
{
    const float* x  = (const float*)d_in[0];
    const float* Wq = (const float*)d_in[1];
    const float* Wk = (const float*)d_in[2];
    const float* Wv = (const float*)d_in[3];
    const float* Wo = (const float*)d_in[4];
    const float* bo = (const float*)d_in[5];
    float* out = (float*)d_out;

    conv_x_kernel<<<1024, 256>>>(x);
    conv_w_kernel<<<640, 256>>>(Wq, Wk, Wv, Wo);

    dim3 gq(S_LEN / 128, HALF / 64, 3);
    qkv_h_kernel<<<gq, 256>>>();

    dim3 ga(S_LEN / 128, NHEAD);
    attn_kernel<<<ga, 128>>>();

    dim3 gp(S_LEN / 128, EMB / 64);
    proj_h_kernel<<<gp, 256>>>(bo, out);
}